// round 13
// baseline (speedup 1.0000x reference)
#include <cuda_runtime.h>
#include <cuda_fp16.h>
#include <math.h>
#include <stdint.h>

// ---------------- problem constants ----------------
#define S_   1024
#define H_   4096
#define NH_  32
#define NKV_ 8
#define HD_  128
#define NREP_ 4        // NH/NKV
#define IS_  11008
#define L_   2
#define EPS_ 1e-5f

// ---------------- scratch (device globals; no runtime alloc allowed) -------
__device__ float g_inv [4096];                            // per-row inv-rms
__device__ float g_q   [(size_t)S_ * H_];                 // Q
__device__ float g_kv  [(size_t)2 * S_ * NKV_ * HD_];     // K then V scratch
__device__ float g_vt  [(size_t)NKV_ * HD_ * S_];         // V^T [kv, d, s]
__device__ float g_sc  [(size_t)NH_ * S_ * S_];           // attention scores
__device__ float g_at  [(size_t)S_ * H_];                 // attn output
__device__ float g_ga  [(size_t)S_ * IS_];                // gate
__device__ float g_up  [(size_t)S_ * IS_];                // up

// =================== helpers ===============================================
__device__ __forceinline__ uint32_t smem_u32(const void* p) {
    uint32_t a;
    asm("{ .reg .u64 t; cvta.to.shared.u64 t, %1; cvt.u32.u64 %0, t; }"
        : "=r"(a) : "l"(p));
    return a;
}

__device__ __forceinline__ void ldm4(uint32_t* r, uint32_t addr) {
    asm volatile("ldmatrix.sync.aligned.m8n8.x4.shared.b16 {%0,%1,%2,%3}, [%4];"
        : "=r"(r[0]), "=r"(r[1]), "=r"(r[2]), "=r"(r[3]) : "r"(addr));
}

// main pass: f16 x f16 -> f32 acc
__device__ __forceinline__ void mma_f32(float* c, const uint32_t* a,
                                        const uint32_t* b) {
    asm("mma.sync.aligned.m16n8k16.row.col.f32.f16.f16.f32 "
        "{%0,%1,%2,%3}, {%4,%5,%6,%7}, {%8,%9}, {%0,%1,%2,%3};"
        : "+f"(c[0]), "+f"(c[1]), "+f"(c[2]), "+f"(c[3])
        : "r"(a[0]), "r"(a[1]), "r"(a[2]), "r"(a[3]), "r"(b[0]), "r"(b[1]));
}

// cross pass: f16 x f16 -> f16 acc (packed x2)
__device__ __forceinline__ void mma_h(uint32_t* c, const uint32_t* a,
                                      const uint32_t* b) {
    asm("mma.sync.aligned.m16n8k16.row.col.f16.f16.f16.f16 "
        "{%0,%1}, {%2,%3,%4,%5}, {%6,%7}, {%0,%1};"
        : "+r"(c[0]), "+r"(c[1])
        : "r"(a[0]), "r"(a[1]), "r"(a[2]), "r"(a[3]), "r"(b[0]), "r"(b[1]));
}

// split 8 fp32 -> 8 f16 hi + 8 f16 lo' (residual x2048)
__device__ __forceinline__ void cvt_chunk(float4 f0, float4 f1,
                                          uint4& hi, uint4& lo) {
    float f[8] = {f0.x, f0.y, f0.z, f0.w, f1.x, f1.y, f1.z, f1.w};
    uint32_t h[4], l[4];
#pragma unroll
    for (int i = 0; i < 4; i++) {
        asm("cvt.rn.f16x2.f32 %0, %1, %2;"
            : "=r"(h[i]) : "f"(f[2 * i + 1]), "f"(f[2 * i]));
        __half2 hb = *reinterpret_cast<__half2*>(&h[i]);
        float2 fb = __half22float2(hb);
        float r0 = (f[2 * i]     - fb.x) * 2048.f;
        float r1 = (f[2 * i + 1] - fb.y) * 2048.f;
        asm("cvt.rn.f16x2.f32 %0, %1, %2;"
            : "=r"(l[i]) : "f"(r1), "f"(r0));
    }
    hi = make_uint4(h[0], h[1], h[2], h[3]);
    lo = make_uint4(l[0], l[1], l[2], l[3]);
}

// round 8 fp32 -> 8 f16 (hi only, for B)
__device__ __forceinline__ void cvt_chunk_h(float4 f0, float4 f1, uint4& hi) {
    uint32_t h[4];
    asm("cvt.rn.f16x2.f32 %0, %1, %2;" : "=r"(h[0]) : "f"(f0.y), "f"(f0.x));
    asm("cvt.rn.f16x2.f32 %0, %1, %2;" : "=r"(h[1]) : "f"(f0.w), "f"(f0.z));
    asm("cvt.rn.f16x2.f32 %0, %1, %2;" : "=r"(h[2]) : "f"(f1.y), "f"(f1.x));
    asm("cvt.rn.f16x2.f32 %0, %1, %2;" : "=r"(h[3]) : "f"(f1.w), "f"(f1.z));
    hi = make_uint4(h[0], h[1], h[2], h[3]);
}

// -------- mbarrier primitives ----------------------------------------------
#define MBAR_INIT(addr, cnt) \
    asm volatile("mbarrier.init.shared.b64 [%0], %1;" :: "r"(addr), "r"((uint32_t)(cnt)) : "memory")
#define MBAR_ARRIVE(addr) \
    asm volatile("mbarrier.arrive.shared.b64 _, [%0];" :: "r"(addr) : "memory")
#define MBAR_WAIT(mbar_addr, parity) do {                                        \
    uint32_t _m = (uint32_t)(mbar_addr);                                         \
    uint32_t _p = (uint32_t)(parity);                                            \
    uint32_t _done;                                                              \
    asm volatile("{\n\t.reg .pred p;\n\t"                                        \
        "mbarrier.try_wait.parity.acquire.cta.shared::cta.b64 p, [%1], %2;\n\t"  \
        "selp.b32 %0, 1, 0, p;\n\t}"                                             \
        : "=r"(_done) : "r"(_m), "r"(_p) : "memory");                            \
    if (!_done) {                                                                \
        asm volatile("{\n\t.reg .pred P1;\n\t"                                   \
            "WAIT_LOOP_%=:\n\t"                                                  \
            "mbarrier.try_wait.parity.acquire.cta.shared::cta.b64 P1, [%0], %1, 0x989680;\n\t" \
            "@P1 bra.uni WAIT_DONE_%=;\n\t"                                      \
            "bra.uni WAIT_LOOP_%=;\n\t"                                          \
            "WAIT_DONE_%=:\n\t}"                                                 \
            :: "r"(_m), "r"(_p) : "memory");                                     \
    }                                                                            \
} while (0)

// ===== warp-specialized 2-pass split-f16 GEMM ==============================
// C[M,N] (+)= A[M,K]*B[N,K]^T  computed as A * f16(B):
//   pass 1: Ah*Bh (f32 acc); pass 2: Al'*Bh (f16 acc, Al' = (A-Ah)*2048)
//   epilogue: C = acc + accX/2048.  B rounding error ~1.4e-4 relative.
// CTA tile 128x128, K-tile 32, 4-stage ring; 8 consumer + 4 producer warps.
// Stage 24KB: Ah@0 Al'@8192 Bh@16384; 64B rows, chunk swz c ^= (row>>1)&3.
#define NSTAGE 4
#define STAGE_B 24576
#define SMEM_DYN (NSTAGE * STAGE_B)

struct GP {
    const float* A; int lda; long long sAz;
    const float* B0; float* C0; int ldb0, ldc0;
    const float* B1; float* C1; int ldb1, ldc1;
    const float* B2; float* C2; int ldb2, ldc2;
    int y1, y2;
    long long sBz, sCz; int zdiv;
    int K; int nsplit; int flags;
    const float* w; const float* inv;
};

__device__ __forceinline__ void prod_load(const float* aRow, const float* bRow,
                                          int kt, float4 (&buf)[16]) {
    const float* as = aRow + kt * 32;
    const float* bs = bRow + kt * 32;
#pragma unroll
    for (int i = 0; i < 8; i++) {
        buf[i]     = *reinterpret_cast<const float4*>(as + 4 * i);
        buf[8 + i] = *reinterpret_cast<const float4*>(bs + 4 * i);
    }
}

__device__ __forceinline__ void prod_step(const float* aRow, const float* bRow,
                                          char* dsm, uint32_t mb,
                                          const uint32_t* off,
                                          const float* wb, float rs,
                                          int kt, int nkt,
                                          float4 (&cur)[16], float4 (&nxt)[16]) {
    if (kt + 1 < nkt) prod_load(aRow, bRow, kt + 1, nxt);
    const int s = kt & (NSTAGE - 1);
    const int r = kt >> 2;
    if (r > 0) MBAR_WAIT(mb + 8 * (NSTAGE + s), (r - 1) & 1);
    if (wb) {
        const float4* wv = reinterpret_cast<const float4*>(wb + kt * 32);
#pragma unroll
        for (int i = 0; i < 8; i++) {
            float4 wz = wv[i];
            cur[i].x *= rs * wz.x; cur[i].y *= rs * wz.y;
            cur[i].z *= rs * wz.z; cur[i].w *= rs * wz.w;
        }
    }
    char* base = dsm + (size_t)s * STAGE_B;
#pragma unroll
    for (int c = 0; c < 4; c++) {
        uint4 hi, lo;
        cvt_chunk(cur[2 * c], cur[2 * c + 1], hi, lo);
        *reinterpret_cast<uint4*>(base + off[c]) = hi;
        *reinterpret_cast<uint4*>(base + 8192 + off[c]) = lo;
    }
#pragma unroll
    for (int c = 0; c < 4; c++) {
        uint4 hi;
        cvt_chunk_h(cur[8 + 2 * c], cur[9 + 2 * c], hi);
        *reinterpret_cast<uint4*>(base + 16384 + off[c]) = hi;
    }
    MBAR_ARRIVE(mb + 8 * s);
}

__global__ __launch_bounds__(384, 1)
void gemm_ws(GP p)
{
    const int bx = blockIdx.x;
    const int byg = blockIdx.y;
    if ((p.flags & 1) && byg > bx) return;
    int K = p.K;
    if (p.flags & 2) {
        int kb = (bx + 1) * 128;
        if (kb < K) K = kb;
    }

    const float* B; float* C; int ldb, ldc; int by = byg;
    if (byg >= p.y2)      { B = p.B2; C = p.C2; ldb = p.ldb2; ldc = p.ldc2; by = byg - p.y2; }
    else if (byg >= p.y1) { B = p.B1; C = p.C1; ldb = p.ldb1; ldc = p.ldc1; by = byg - p.y1; }
    else                  { B = p.B0; C = p.C0; ldb = p.ldb0; ldc = p.ldc0; }

    int split = 0, zz = blockIdx.z;
    if (p.nsplit > 1) { split = blockIdx.z; zz = 0; }
    const int nktT = K / 32;
    const int kt0 = (nktT * split) / p.nsplit;
    const int kt1 = (nktT * (split + 1)) / p.nsplit;
    const int nkt = kt1 - kt0;

    const float* Ap = p.A + (long long)bx * 128 * p.lda + (long long)zz * p.sAz + kt0 * 32;
    const float* Bp = B + (long long)by * 128 * ldb + (long long)(zz / p.zdiv) * p.sBz + kt0 * 32;
    float* Cp = C + (long long)bx * 128 * ldc + (long long)by * 128 + (long long)zz * p.sCz;

    extern __shared__ char dsm[];
    __shared__ uint64_t mbar[2 * NSTAGE];
    const uint32_t sb = smem_u32(dsm);
    const uint32_t mb = smem_u32(mbar);
    const int tid = threadIdx.x;
    const int wid = tid >> 5, lid = tid & 31;

    if (tid == 0) {
#pragma unroll
        for (int i = 0; i < NSTAGE; i++) {
            MBAR_INIT(mb + 8 * i, 128);
            MBAR_INIT(mb + 8 * (NSTAGE + i), 256);
        }
    }
    __syncthreads();

    if (wid >= 8) {
        // ================= producer =================
        const int prow = tid - 256;
        const float* aRow = Ap + (long long)prow * p.lda;
        const float* bRow = Bp + (long long)prow * ldb;
        float rs = 0.f;
        const float* wb = nullptr;
        if (p.w) { rs = p.inv[bx * 128 + prow]; wb = p.w + kt0 * 32; }
        const uint32_t rsw = ((uint32_t)(prow >> 1) & 3u);
        uint32_t off[4];
#pragma unroll
        for (int c = 0; c < 4; c++)
            off[c] = (uint32_t)prow * 64 + (((uint32_t)c ^ rsw) << 4);

        float4 buf0[16], buf1[16];
        prod_load(aRow, bRow, 0, buf0);
        for (int kt = 0; kt < nkt; kt += 2) {
            prod_step(aRow, bRow, dsm, mb, off, wb, rs, kt, nkt, buf0, buf1);
            if (kt + 1 < nkt)
                prod_step(aRow, bRow, dsm, mb, off, wb, rs, kt + 1, nkt, buf1, buf0);
        }
        return;
    }

    // ================= consumer =================
    const int wm = wid & 3, wn = wid >> 2;
    float    acc [2][8][4] = {};
    uint32_t accX[2][8][2] = {};    // f16x2 packed cross accumulators

    uint32_t aAddr[2], bAddr[4];
    {
        int j = lid >> 3, rin = lid & 7;
#pragma unroll
        for (int mt = 0; mt < 2; mt++) {
            int row = wm * 32 + mt * 16 + (j & 1) * 8 + rin;
            int ch = (j >> 1);
            aAddr[mt] = sb + (uint32_t)row * 64
                      + ((uint32_t)(ch ^ ((row >> 1) & 3)) << 4);
        }
#pragma unroll
        for (int q = 0; q < 4; q++) {
            int row = wn * 64 + q * 16 + (j >> 1) * 8 + rin;
            int ch = (j & 1);
            bAddr[q] = sb + 16384u + (uint32_t)row * 64
                     + ((uint32_t)(ch ^ ((row >> 1) & 3)) << 4);
        }
    }

    for (int kt = 0; kt < nkt; kt++) {
        const int s = kt & (NSTAGE - 1);
        const uint32_t stg = (uint32_t)s * STAGE_B;
        MBAR_WAIT(mb + 8 * s, (kt >> 2) & 1);

#pragma unroll
        for (int s16 = 0; s16 < 2; s16++) {
            const uint32_t sx = (uint32_t)s16 << 5;
            uint32_t ah[2][4], bh[8][2];
#pragma unroll
            for (int mt = 0; mt < 2; mt++)
                ldm4(ah[mt], (aAddr[mt] + stg) ^ sx);
#pragma unroll
            for (int q = 0; q < 4; q++) {
                uint32_t t4[4];
                ldm4(t4, (bAddr[q] + stg) ^ sx);
                bh[2 * q][0] = t4[0]; bh[2 * q][1] = t4[1];
                bh[2 * q + 1][0] = t4[2]; bh[2 * q + 1][1] = t4[3];
            }
            // main pass: Ah*Bh, f32 acc
#pragma unroll
            for (int nt = 0; nt < 8; nt++)
#pragma unroll
                for (int mt = 0; mt < 2; mt++)
                    mma_f32(acc[mt][nt], ah[mt], bh[nt]);
            // load Al', cross pass Al'*Bh (f16 acc)
            {
                uint32_t al[2][4];
#pragma unroll
                for (int mt = 0; mt < 2; mt++)
                    ldm4(al[mt], (aAddr[mt] + stg + 8192u) ^ sx);
                if (s16 == 1) MBAR_ARRIVE(mb + 8 * (NSTAGE + s));
#pragma unroll
                for (int nt = 0; nt < 8; nt++)
#pragma unroll
                    for (int mt = 0; mt < 2; mt++)
                        mma_h(accX[mt][nt], al[mt], bh[nt]);
            }
        }
    }

    // epilogue: C = acc + unpack(accX)/2048
    const float XS = 1.0f / 2048.0f;
    const int er = wm * 32 + (lid >> 2);
    const int ec = wn * 64 + 2 * (lid & 3);
#pragma unroll
    for (int mt = 0; mt < 2; mt++) {
#pragma unroll
        for (int nt = 0; nt < 8; nt++) {
            __half2 h0 = *reinterpret_cast<__half2*>(&accX[mt][nt][0]);
            __half2 h1 = *reinterpret_cast<__half2*>(&accX[mt][nt][1]);
            float2 x01 = __half22float2(h0);
            float2 x23 = __half22float2(h1);
            float v0 = acc[mt][nt][0] + x01.x * XS;
            float v1 = acc[mt][nt][1] + x01.y * XS;
            float v2 = acc[mt][nt][2] + x23.x * XS;
            float v3 = acc[mt][nt][3] + x23.y * XS;
            float* cp = Cp + (long long)(er + mt * 16) * ldc + ec + nt * 8;
            if (p.nsplit > 1) {
                atomicAdd(cp + 0, v0);
                atomicAdd(cp + 1, v1);
                atomicAdd(cp + 8 * (long long)ldc + 0, v2);
                atomicAdd(cp + 8 * (long long)ldc + 1, v3);
            } else {
                *reinterpret_cast<float2*>(cp) = make_float2(v0, v1);
                *reinterpret_cast<float2*>(cp + 8 * (long long)ldc) =
                    make_float2(v2, v3);
            }
        }
    }
}

// ---------------- inv-rms per row ------------------------------------------
__global__ __launch_bounds__(256)
void invnorm_k(const float* __restrict__ h, float* __restrict__ inv)
{
    const int row = blockIdx.x * 8 + (threadIdx.x >> 5);
    const int lane = threadIdx.x & 31;
    const float4* hr = reinterpret_cast<const float4*>(h + (size_t)row * H_);
    float ss = 0.f;
#pragma unroll
    for (int i = 0; i < 32; i++) {
        float4 v = hr[lane + i * 32];
        ss += v.x * v.x + v.y * v.y + v.z * v.z + v.w * v.w;
    }
#pragma unroll
    for (int o = 16; o > 0; o >>= 1) ss += __shfl_xor_sync(0xffffffffu, ss, o);
    if (lane == 0) inv[row] = rsqrtf(ss / (float)H_ + EPS_);
}

// ---------------- RoPE ------------------------------------------------------
__global__ __launch_bounds__(256)
void rope_k(float* __restrict__ q,
            const float* __restrict__ kin, const float* __restrict__ vin,
            const int* __restrict__ pos,
            const float* __restrict__ cosT, const float* __restrict__ sinT,
            float* __restrict__ keys_l, float* __restrict__ vals_l,
            float* __restrict__ vt, float scale)
{
    const int s = blockIdx.x;
    const int p = pos[s];
    const float* cb = cosT + (size_t)p * HD_;
    const float* sb = sinT + (size_t)p * HD_;

#pragma unroll
    for (int i = 0; i < 8; i++) {
        int pi = threadIdx.x + i * 256;
        int hh = pi >> 6, d = pi & 63;
        float c0 = cb[d], c1 = cb[d + 64], s0 = sb[d], s1 = sb[d + 64];
        float* qp = q + (size_t)s * H_ + hh * HD_;
        float a = qp[d], b = qp[d + 64];
        qp[d]      = (a * c0 - b * s0) * scale;
        qp[d + 64] = (b * c1 + a * s1) * scale;
    }
#pragma unroll
    for (int i = 0; i < 2; i++) {
        int pi = threadIdx.x + i * 256;
        int kv = pi >> 6, d = pi & 63;
        float c0 = cb[d], c1 = cb[d + 64], s0 = sb[d], s1 = sb[d + 64];
        const float* kp = kin + (size_t)s * (NKV_ * HD_) + kv * HD_;
        const float* vp = vin + (size_t)s * (NKV_ * HD_) + kv * HD_;
        float a = kp[d], b = kp[d + 64];
        size_t ob = (size_t)kv * S_ * HD_ + (size_t)s * HD_;
        keys_l[ob + d]      = a * c0 - b * s0;
        keys_l[ob + d + 64] = b * c1 + a * s1;
        float v0 = vp[d], v1 = vp[d + 64];
        vals_l[ob + d] = v0;
        vals_l[ob + d + 64] = v1;
        vt[((size_t)kv * HD_ + d) * S_ + s] = v0;
        vt[((size_t)kv * HD_ + d + 64) * S_ + s] = v1;
    }
}

// ------- softmax (mask + softmax; scale pre-folded into Q), causal prefix --
__global__ __launch_bounds__(256)
void softmax_k(float* __restrict__ scores, const float* __restrict__ mask)
{
    const int q = blockIdx.x;
    const int h = blockIdx.y;
    float* row = scores + ((size_t)h * S_ + q) * (size_t)S_;
    const float* m = mask + (size_t)q * S_;
    const int Lq = ((q >> 7) + 1) << 7;
    const int nt = (Lq + 255) >> 8;

    float v[4];
    float mx = -1e30f;
#pragma unroll
    for (int t = 0; t < 4; t++) {
        v[t] = -1e30f;
        if (t < nt) {
            int j = threadIdx.x + t * 256;
            if (j < Lq) {
                v[t] = row[j] + m[j];
                mx = fmaxf(mx, v[t]);
            }
        }
    }
#pragma unroll
    for (int o = 16; o > 0; o >>= 1) mx = fmaxf(mx, __shfl_xor_sync(0xffffffffu, mx, o));
    __shared__ float smx[8];
    __shared__ float ssum[8];
    if ((threadIdx.x & 31) == 0) smx[threadIdx.x >> 5] = mx;
    __syncthreads();
    float rmx = smx[0];
#pragma unroll
    for (int i = 1; i < 8; i++) rmx = fmaxf(rmx, smx[i]);

    float sum = 0.f;
#pragma unroll
    for (int t = 0; t < 4; t++) {
        if (t < nt) {
            int j = threadIdx.x + t * 256;
            if (j < Lq) {
                v[t] = expf(v[t] - rmx);
                sum += v[t];
            }
        }
    }
#pragma unroll
    for (int o = 16; o > 0; o >>= 1) sum += __shfl_xor_sync(0xffffffffu, sum, o);
    if ((threadIdx.x & 31) == 0) ssum[threadIdx.x >> 5] = sum;
    __syncthreads();
    float rsum = ssum[0];
#pragma unroll
    for (int i = 1; i < 8; i++) rsum += ssum[i];
    float inv = 1.f / rsum;
#pragma unroll
    for (int t = 0; t < 4; t++) {
        if (t < nt) {
            int j = threadIdx.x + t * 256;
            if (j < Lq) row[j] = v[t] * inv;
        }
    }
}

// ---------------- silu(gate) * up ------------------------------------------
__global__ __launch_bounds__(256)
void silu_mul_k(float* __restrict__ g, const float* __restrict__ u, long long n)
{
    long long i = (long long)blockIdx.x * 256 + threadIdx.x;
    if (i < n) {
        float x = g[i];
        g[i] = (x / (1.f + expf(-x))) * u[i];
    }
}

// ---------------- launch ----------------------------------------------------
extern "C" void kernel_launch(void* const* d_in, const int* in_sizes, int n_in,
                              void* d_out, int out_size)
{
    const float* x     = (const float*)d_in[0];
    const float* mask  = (const float*)d_in[1];
    const int*   pos   = (const int*)  d_in[2];
    const float* cos_t = (const float*)d_in[3];
    const float* sin_t = (const float*)d_in[4];
    const float* ln1   = (const float*)d_in[5];
    const float* ln2   = (const float*)d_in[6];
    const float* qw    = (const float*)d_in[7];
    const float* kw    = (const float*)d_in[8];
    const float* vw    = (const float*)d_in[9];
    const float* ow    = (const float*)d_in[10];
    const float* gw    = (const float*)d_in[11];
    const float* uw    = (const float*)d_in[12];
    const float* dw    = (const float*)d_in[13];

    float* out  = (float*)d_out;
    float* h    = out;
    float* keys = out + (size_t)S_ * H_;
    float* vals = keys + (size_t)L_ * NKV_ * S_ * HD_;

    float *inv_, *q_, *kv_, *vt_, *sc_, *at_, *ga_, *up_;
    cudaGetSymbolAddress((void**)&inv_, g_inv);
    cudaGetSymbolAddress((void**)&q_,  g_q);
    cudaGetSymbolAddress((void**)&kv_, g_kv);
    cudaGetSymbolAddress((void**)&vt_, g_vt);
    cudaGetSymbolAddress((void**)&sc_, g_sc);
    cudaGetSymbolAddress((void**)&at_, g_at);
    cudaGetSymbolAddress((void**)&ga_, g_ga);
    cudaGetSymbolAddress((void**)&up_, g_up);

    cudaFuncSetAttribute(gemm_ws,
                         cudaFuncAttributeMaxDynamicSharedMemorySize, SMEM_DYN);

    const float scale = 1.f / sqrtf((float)HD_);
    const int BIG = 1 << 30;

    cudaMemcpyAsync(h, x, (size_t)S_ * H_ * sizeof(float),
                    cudaMemcpyDeviceToDevice, 0);

    for (int l = 0; l < L_; l++) {
        const float* qwl = qw + (size_t)l * (NH_ * HD_) * H_;
        const float* kwl = kw + (size_t)l * (NKV_ * HD_) * H_;
        const float* vwl = vw + (size_t)l * (NKV_ * HD_) * H_;
        const float* owl = ow + (size_t)l * H_ * (NH_ * HD_);
        const float* gwl = gw + (size_t)l * IS_ * H_;
        const float* uwl = uw + (size_t)l * IS_ * H_;
        const float* dwl = dw + (size_t)l * H_ * IS_;
        float* keys_l = keys + (size_t)l * NKV_ * S_ * HD_;
        float* vals_l = vals + (size_t)l * NKV_ * S_ * HD_;
        float* kscr = kv_;
        float* vscr = kv_ + (size_t)S_ * NKV_ * HD_;

        // ---- attention block ----
        invnorm_k<<<S_ / 8, 256>>>(h, inv_);

        cudaMemsetAsync(q_,  0, (size_t)S_ * H_ * sizeof(float), 0);
        cudaMemsetAsync(kv_, 0, (size_t)2 * S_ * NKV_ * HD_ * sizeof(float), 0);
        {
            GP p = {};
            p.A = h; p.lda = H_; p.sAz = 0;
            p.B0 = qwl; p.C0 = q_;   p.ldb0 = H_; p.ldc0 = H_;
            p.B1 = kwl; p.C1 = kscr; p.ldb1 = H_; p.ldc1 = NKV_ * HD_;
            p.B2 = vwl; p.C2 = vscr; p.ldb2 = H_; p.ldc2 = NKV_ * HD_;
            p.y1 = 32; p.y2 = 40;
            p.sBz = 0; p.sCz = 0; p.zdiv = 1;
            p.K = H_; p.nsplit = 3; p.flags = 0;
            p.w = ln1 + (size_t)l * H_; p.inv = inv_;
            gemm_ws<<<dim3(8, 48, 3), 384, SMEM_DYN>>>(p);
        }

        rope_k<<<S_, 256>>>(q_, kscr, vscr, pos, cos_t, sin_t,
                            keys_l, vals_l, vt_, scale);

        {
            GP p = {};
            p.A = q_; p.lda = H_; p.sAz = HD_;
            p.B0 = keys_l; p.C0 = sc_; p.ldb0 = HD_; p.ldc0 = S_;
            p.y1 = BIG; p.y2 = BIG;
            p.sBz = (long long)S_ * HD_; p.sCz = (long long)S_ * S_; p.zdiv = NREP_;
            p.K = HD_; p.nsplit = 1; p.flags = 1;
            gemm_ws<<<dim3(8, 8, NH_), 384, SMEM_DYN>>>(p);
        }

        softmax_k<<<dim3(S_, NH_), 256>>>(sc_, mask);

        {
            GP p = {};
            p.A = sc_; p.lda = S_; p.sAz = (long long)S_ * S_;
            p.B0 = vt_; p.C0 = at_; p.ldb0 = S_; p.ldc0 = H_;
            p.y1 = BIG; p.y2 = BIG;
            p.sBz = (long long)HD_ * S_; p.sCz = HD_; p.zdiv = NREP_;
            p.K = S_; p.nsplit = 1; p.flags = 2;
            gemm_ws<<<dim3(8, 1, NH_), 384, SMEM_DYN>>>(p);
        }

        {
            GP p = {};
            p.A = at_; p.lda = H_; p.sAz = 0;
            p.B0 = owl; p.C0 = h; p.ldb0 = H_; p.ldc0 = H_;
            p.y1 = BIG; p.y2 = BIG;
            p.sBz = 0; p.sCz = 0; p.zdiv = 1;
            p.K = H_; p.nsplit = 4; p.flags = 0;
            gemm_ws<<<dim3(8, 32, 4), 384, SMEM_DYN>>>(p);
        }

        // ---- MLP block ----
        invnorm_k<<<S_ / 8, 256>>>(h, inv_ + 2048);

        cudaMemsetAsync(ga_, 0, (size_t)S_ * IS_ * sizeof(float), 0);
        cudaMemsetAsync(up_, 0, (size_t)S_ * IS_ * sizeof(float), 0);
        {
            GP p = {};
            p.A = h; p.lda = H_; p.sAz = 0;
            p.B0 = gwl; p.C0 = ga_; p.ldb0 = H_; p.ldc0 = IS_;
            p.B1 = uwl; p.C1 = up_; p.ldb1 = H_; p.ldc1 = IS_;
            p.y1 = 86; p.y2 = BIG;
            p.sBz = 0; p.sCz = 0; p.zdiv = 1;
            p.K = H_; p.nsplit = 2; p.flags = 0;
            p.w = ln2 + (size_t)l * H_; p.inv = inv_ + 2048;
            gemm_ws<<<dim3(8, 172, 2), 384, SMEM_DYN>>>(p);
        }

        long long nel = (long long)S_ * IS_;
        silu_mul_k<<<(unsigned)((nel + 255) / 256), 256>>>(ga_, up_, nel);

        {
            GP p = {};
            p.A = ga_; p.lda = IS_; p.sAz = 0;
            p.B0 = dwl; p.C0 = h; p.ldb0 = IS_; p.ldc0 = H_;
            p.y1 = BIG; p.y2 = BIG;
            p.sBz = 0; p.sCz = 0; p.zdiv = 1;
            p.K = IS_; p.nsplit = 4; p.flags = 0;
            gemm_ws<<<dim3(8, 32, 4), 384, SMEM_DYN>>>(p);
        }
    }
}

// round 15
// speedup vs baseline: 1.4787x; 1.4787x over previous
#include <cuda_runtime.h>
#include <cuda_fp16.h>
#include <math.h>
#include <stdint.h>

// ---------------- problem constants ----------------
#define S_   1024
#define H_   4096
#define NH_  32
#define NKV_ 8
#define HD_  128
#define NREP_ 4        // NH/NKV
#define IS_  11008
#define L_   2
#define EPS_ 1e-5f

// ---------------- scratch (device globals; no runtime alloc allowed) -------
__device__ float g_inv [4096];                            // per-row inv-rms
__device__ float g_q   [(size_t)S_ * H_];                 // Q
__device__ float g_kv  [(size_t)2 * S_ * NKV_ * HD_];     // K then V scratch
__device__ float g_vt  [(size_t)NKV_ * HD_ * S_];         // V^T [kv, d, s]
__device__ float g_sc  [(size_t)NH_ * S_ * S_];           // attention scores
__device__ float g_at  [(size_t)S_ * H_];                 // attn output
__device__ float g_ga  [(size_t)S_ * IS_];                // gate
__device__ float g_up  [(size_t)S_ * IS_];                // up

// =================== helpers ===============================================
__device__ __forceinline__ uint32_t smem_u32(const void* p) {
    uint32_t a;
    asm("{ .reg .u64 t; cvta.to.shared.u64 t, %1; cvt.u32.u64 %0, t; }"
        : "=r"(a) : "l"(p));
    return a;
}

__device__ __forceinline__ void ldm4(uint32_t* r, uint32_t addr) {
    asm volatile("ldmatrix.sync.aligned.m8n8.x4.shared.b16 {%0,%1,%2,%3}, [%4];"
        : "=r"(r[0]), "=r"(r[1]), "=r"(r[2]), "=r"(r[3]) : "r"(addr));
}

// f16 x f16 -> f32 acc
__device__ __forceinline__ void mma_f32(float* c, const uint32_t* a,
                                        const uint32_t* b) {
    asm("mma.sync.aligned.m16n8k16.row.col.f32.f16.f16.f32 "
        "{%0,%1,%2,%3}, {%4,%5,%6,%7}, {%8,%9}, {%0,%1,%2,%3};"
        : "+f"(c[0]), "+f"(c[1]), "+f"(c[2]), "+f"(c[3])
        : "r"(a[0]), "r"(a[1]), "r"(a[2]), "r"(a[3]), "r"(b[0]), "r"(b[1]));
}

// f16 x f16 -> f16 acc (packed x2)
__device__ __forceinline__ void mma_h(uint32_t* c, const uint32_t* a,
                                      const uint32_t* b) {
    asm("mma.sync.aligned.m16n8k16.row.col.f16.f16.f16.f16 "
        "{%0,%1}, {%2,%3,%4,%5}, {%6,%7}, {%0,%1};"
        : "+r"(c[0]), "+r"(c[1])
        : "r"(a[0]), "r"(a[1]), "r"(a[2]), "r"(a[3]), "r"(b[0]), "r"(b[1]));
}

// split 8 fp32 -> 8 f16 hi + 8 f16 lo' (residual x2048)
__device__ __forceinline__ void cvt_chunk(float4 f0, float4 f1,
                                          uint4& hi, uint4& lo) {
    float f[8] = {f0.x, f0.y, f0.z, f0.w, f1.x, f1.y, f1.z, f1.w};
    uint32_t h[4], l[4];
#pragma unroll
    for (int i = 0; i < 4; i++) {
        asm("cvt.rn.f16x2.f32 %0, %1, %2;"
            : "=r"(h[i]) : "f"(f[2 * i + 1]), "f"(f[2 * i]));
        __half2 hb = *reinterpret_cast<__half2*>(&h[i]);
        float2 fb = __half22float2(hb);
        float r0 = (f[2 * i]     - fb.x) * 2048.f;
        float r1 = (f[2 * i + 1] - fb.y) * 2048.f;
        asm("cvt.rn.f16x2.f32 %0, %1, %2;"
            : "=r"(l[i]) : "f"(r1), "f"(r0));
    }
    hi = make_uint4(h[0], h[1], h[2], h[3]);
    lo = make_uint4(l[0], l[1], l[2], l[3]);
}

// round 8 fp32 -> 8 f16 (hi only)
__device__ __forceinline__ void cvt_chunk_h(float4 f0, float4 f1, uint4& hi) {
    uint32_t h[4];
    asm("cvt.rn.f16x2.f32 %0, %1, %2;" : "=r"(h[0]) : "f"(f0.y), "f"(f0.x));
    asm("cvt.rn.f16x2.f32 %0, %1, %2;" : "=r"(h[1]) : "f"(f0.w), "f"(f0.z));
    asm("cvt.rn.f16x2.f32 %0, %1, %2;" : "=r"(h[2]) : "f"(f1.y), "f"(f1.x));
    asm("cvt.rn.f16x2.f32 %0, %1, %2;" : "=r"(h[3]) : "f"(f1.w), "f"(f1.z));
    hi = make_uint4(h[0], h[1], h[2], h[3]);
}

// -------- mbarrier primitives ----------------------------------------------
#define MBAR_INIT(addr, cnt) \
    asm volatile("mbarrier.init.shared.b64 [%0], %1;" :: "r"(addr), "r"((uint32_t)(cnt)) : "memory")
#define MBAR_ARRIVE(addr) \
    asm volatile("mbarrier.arrive.shared.b64 _, [%0];" :: "r"(addr) : "memory")
#define MBAR_WAIT(mbar_addr, parity) do {                                        \
    uint32_t _m = (uint32_t)(mbar_addr);                                         \
    uint32_t _p = (uint32_t)(parity);                                            \
    uint32_t _done;                                                              \
    asm volatile("{\n\t.reg .pred p;\n\t"                                        \
        "mbarrier.try_wait.parity.acquire.cta.shared::cta.b64 p, [%1], %2;\n\t"  \
        "selp.b32 %0, 1, 0, p;\n\t}"                                             \
        : "=r"(_done) : "r"(_m), "r"(_p) : "memory");                            \
    if (!_done) {                                                                \
        asm volatile("{\n\t.reg .pred P1;\n\t"                                   \
            "WAIT_LOOP_%=:\n\t"                                                  \
            "mbarrier.try_wait.parity.acquire.cta.shared::cta.b64 P1, [%0], %1, 0x989680;\n\t" \
            "@P1 bra.uni WAIT_DONE_%=;\n\t"                                      \
            "bra.uni WAIT_LOOP_%=;\n\t"                                          \
            "WAIT_DONE_%=:\n\t}"                                                 \
            :: "r"(_m), "r"(_p) : "memory");                                     \
    }                                                                            \
} while (0)

// ===== warp-specialized split-f16 GEMM (NP = 2 or 3 passes) ================
// NP==3: C = Ah*Bh (f32) + (Ah*Bl' + Al'*Bh)/2048   (exact-class, ~1e-5)
// NP==2: C = Ah*Bh (f32) + (Al'*Bh)/2048, B rounded  (~1.4e-4 per GEMM)
// CTA tile 128x128, K-tile 32, 4-stage ring; 8 consumer + 4 producer warps.
// Stage 32KB: Ah@0 Al'@8192 Bh@16384 Bl'@24576 (Bl unused when NP==2).
#define NSTAGE 4
#define STAGE_B 32768
#define SMEM_DYN (NSTAGE * STAGE_B)

struct GP {
    const float* A; int lda; long long sAz;
    const float* B0; float* C0; int ldb0, ldc0;
    const float* B1; float* C1; int ldb1, ldc1;
    const float* B2; float* C2; int ldb2, ldc2;
    int y1, y2;
    long long sBz, sCz; int zdiv;
    int K; int nsplit; int flags;
    const float* w; const float* inv;
};

__device__ __forceinline__ void prod_load(const float* aRow, const float* bRow,
                                          int kt, float4 (&buf)[16]) {
    const float* as = aRow + kt * 32;
    const float* bs = bRow + kt * 32;
#pragma unroll
    for (int i = 0; i < 8; i++) {
        buf[i]     = *reinterpret_cast<const float4*>(as + 4 * i);
        buf[8 + i] = *reinterpret_cast<const float4*>(bs + 4 * i);
    }
}

template<int NP>
__device__ __forceinline__ void prod_step(const float* aRow, const float* bRow,
                                          char* dsm, uint32_t mb,
                                          const uint32_t* off,
                                          const float* wb, float rs,
                                          int kt, int nkt,
                                          float4 (&cur)[16], float4 (&nxt)[16]) {
    if (kt + 1 < nkt) prod_load(aRow, bRow, kt + 1, nxt);
    const int s = kt & (NSTAGE - 1);
    const int r = kt >> 2;
    if (r > 0) MBAR_WAIT(mb + 8 * (NSTAGE + s), (r - 1) & 1);
    if (wb) {
        const float4* wv = reinterpret_cast<const float4*>(wb + kt * 32);
#pragma unroll
        for (int i = 0; i < 8; i++) {
            float4 wz = wv[i];
            cur[i].x *= rs * wz.x; cur[i].y *= rs * wz.y;
            cur[i].z *= rs * wz.z; cur[i].w *= rs * wz.w;
        }
    }
    char* base = dsm + (size_t)s * STAGE_B;
#pragma unroll
    for (int c = 0; c < 4; c++) {
        uint4 hi, lo;
        cvt_chunk(cur[2 * c], cur[2 * c + 1], hi, lo);
        *reinterpret_cast<uint4*>(base + off[c]) = hi;
        *reinterpret_cast<uint4*>(base + 8192 + off[c]) = lo;
    }
    if (NP == 3) {
#pragma unroll
        for (int c = 0; c < 4; c++) {
            uint4 hi, lo;
            cvt_chunk(cur[8 + 2 * c], cur[9 + 2 * c], hi, lo);
            *reinterpret_cast<uint4*>(base + 16384 + off[c]) = hi;
            *reinterpret_cast<uint4*>(base + 24576 + off[c]) = lo;
        }
    } else {
#pragma unroll
        for (int c = 0; c < 4; c++) {
            uint4 hi;
            cvt_chunk_h(cur[8 + 2 * c], cur[9 + 2 * c], hi);
            *reinterpret_cast<uint4*>(base + 16384 + off[c]) = hi;
        }
    }
    MBAR_ARRIVE(mb + 8 * s);
}

template<int NP>
__global__ __launch_bounds__(384, 1)
void gemm_ws(GP p)
{
    const int bx = blockIdx.x;
    const int byg = blockIdx.y;
    if ((p.flags & 1) && byg > bx) return;
    int K = p.K;
    if (p.flags & 2) {
        int kb = (bx + 1) * 128;
        if (kb < K) K = kb;
    }

    const float* B; float* C; int ldb, ldc; int by = byg;
    if (byg >= p.y2)      { B = p.B2; C = p.C2; ldb = p.ldb2; ldc = p.ldc2; by = byg - p.y2; }
    else if (byg >= p.y1) { B = p.B1; C = p.C1; ldb = p.ldb1; ldc = p.ldc1; by = byg - p.y1; }
    else                  { B = p.B0; C = p.C0; ldb = p.ldb0; ldc = p.ldc0; }

    int split = 0, zz = blockIdx.z;
    if (p.nsplit > 1) { split = blockIdx.z; zz = 0; }
    const int nktT = K / 32;
    const int kt0 = (nktT * split) / p.nsplit;
    const int kt1 = (nktT * (split + 1)) / p.nsplit;
    const int nkt = kt1 - kt0;

    const float* Ap = p.A + (long long)bx * 128 * p.lda + (long long)zz * p.sAz + kt0 * 32;
    const float* Bp = B + (long long)by * 128 * ldb + (long long)(zz / p.zdiv) * p.sBz + kt0 * 32;
    float* Cp = C + (long long)bx * 128 * ldc + (long long)by * 128 + (long long)zz * p.sCz;

    extern __shared__ char dsm[];
    __shared__ uint64_t mbar[2 * NSTAGE];
    const uint32_t sb = smem_u32(dsm);
    const uint32_t mb = smem_u32(mbar);
    const int tid = threadIdx.x;
    const int wid = tid >> 5, lid = tid & 31;

    if (tid == 0) {
#pragma unroll
        for (int i = 0; i < NSTAGE; i++) {
            MBAR_INIT(mb + 8 * i, 128);
            MBAR_INIT(mb + 8 * (NSTAGE + i), 256);
        }
    }
    __syncthreads();

    if (wid >= 8) {
        // ================= producer =================
        const int prow = tid - 256;
        const float* aRow = Ap + (long long)prow * p.lda;
        const float* bRow = Bp + (long long)prow * ldb;
        float rs = 0.f;
        const float* wb = nullptr;
        if (p.w) { rs = p.inv[bx * 128 + prow]; wb = p.w + kt0 * 32; }
        const uint32_t rsw = ((uint32_t)(prow >> 1) & 3u);
        uint32_t off[4];
#pragma unroll
        for (int c = 0; c < 4; c++)
            off[c] = (uint32_t)prow * 64 + (((uint32_t)c ^ rsw) << 4);

        float4 buf0[16], buf1[16];
        prod_load(aRow, bRow, 0, buf0);
        for (int kt = 0; kt < nkt; kt += 2) {
            prod_step<NP>(aRow, bRow, dsm, mb, off, wb, rs, kt, nkt, buf0, buf1);
            if (kt + 1 < nkt)
                prod_step<NP>(aRow, bRow, dsm, mb, off, wb, rs, kt + 1, nkt, buf1, buf0);
        }
        return;
    }

    // ================= consumer =================
    const int wm = wid & 3, wn = wid >> 2;
    float    acc [2][8][4] = {};
    uint32_t accX[2][8][2] = {};    // f16x2 packed cross accumulators

    uint32_t aAddr[2], bAddr[4];
    {
        int j = lid >> 3, rin = lid & 7;
#pragma unroll
        for (int mt = 0; mt < 2; mt++) {
            int row = wm * 32 + mt * 16 + (j & 1) * 8 + rin;
            int ch = (j >> 1);
            aAddr[mt] = sb + (uint32_t)row * 64
                      + ((uint32_t)(ch ^ ((row >> 1) & 3)) << 4);
        }
#pragma unroll
        for (int q = 0; q < 4; q++) {
            int row = wn * 64 + q * 16 + (j >> 1) * 8 + rin;
            int ch = (j & 1);
            bAddr[q] = sb + 16384u + (uint32_t)row * 64
                     + ((uint32_t)(ch ^ ((row >> 1) & 3)) << 4);
        }
    }

    for (int kt = 0; kt < nkt; kt++) {
        const int s = kt & (NSTAGE - 1);
        const uint32_t stg = (uint32_t)s * STAGE_B;
        MBAR_WAIT(mb + 8 * s, (kt >> 2) & 1);

#pragma unroll
        for (int s16 = 0; s16 < 2; s16++) {
            const uint32_t sx = (uint32_t)s16 << 5;
            uint32_t ah[2][4], bh[8][2];
#pragma unroll
            for (int mt = 0; mt < 2; mt++)
                ldm4(ah[mt], (aAddr[mt] + stg) ^ sx);
#pragma unroll
            for (int q = 0; q < 4; q++) {
                uint32_t t4[4];
                ldm4(t4, (bAddr[q] + stg) ^ sx);
                bh[2 * q][0] = t4[0]; bh[2 * q][1] = t4[1];
                bh[2 * q + 1][0] = t4[2]; bh[2 * q + 1][1] = t4[3];
            }
            // main pass: Ah*Bh, f32 acc
#pragma unroll
            for (int nt = 0; nt < 8; nt++)
#pragma unroll
                for (int mt = 0; mt < 2; mt++)
                    mma_f32(acc[mt][nt], ah[mt], bh[nt]);
            // cross pass: Al'*Bh (f16 acc)
            {
                uint32_t al[2][4];
#pragma unroll
                for (int mt = 0; mt < 2; mt++)
                    ldm4(al[mt], (aAddr[mt] + stg + 8192u) ^ sx);
                if (NP == 2 && s16 == 1) MBAR_ARRIVE(mb + 8 * (NSTAGE + s));
#pragma unroll
                for (int nt = 0; nt < 8; nt++)
#pragma unroll
                    for (int mt = 0; mt < 2; mt++)
                        mma_h(accX[mt][nt], al[mt], bh[nt]);
            }
            // cross pass 2 (NP==3 only): Ah*Bl' (f16 acc)
            if (NP == 3) {
                uint32_t bl[8][2];
#pragma unroll
                for (int q = 0; q < 4; q++) {
                    uint32_t t4[4];
                    ldm4(t4, (bAddr[q] + stg + 8192u) ^ sx);
                    bl[2 * q][0] = t4[0]; bl[2 * q][1] = t4[1];
                    bl[2 * q + 1][0] = t4[2]; bl[2 * q + 1][1] = t4[3];
                }
                if (s16 == 1) MBAR_ARRIVE(mb + 8 * (NSTAGE + s));
#pragma unroll
                for (int nt = 0; nt < 8; nt++)
#pragma unroll
                    for (int mt = 0; mt < 2; mt++)
                        mma_h(accX[mt][nt], ah[mt], bl[nt]);
            }
        }
    }

    // epilogue: C = acc + unpack(accX)/2048
    const float XS = 1.0f / 2048.0f;
    const int er = wm * 32 + (lid >> 2);
    const int ec = wn * 64 + 2 * (lid & 3);
#pragma unroll
    for (int mt = 0; mt < 2; mt++) {
#pragma unroll
        for (int nt = 0; nt < 8; nt++) {
            __half2 h0 = *reinterpret_cast<__half2*>(&accX[mt][nt][0]);
            __half2 h1 = *reinterpret_cast<__half2*>(&accX[mt][nt][1]);
            float2 x01 = __half22float2(h0);
            float2 x23 = __half22float2(h1);
            float v0 = acc[mt][nt][0] + x01.x * XS;
            float v1 = acc[mt][nt][1] + x01.y * XS;
            float v2 = acc[mt][nt][2] + x23.x * XS;
            float v3 = acc[mt][nt][3] + x23.y * XS;
            float* cp = Cp + (long long)(er + mt * 16) * ldc + ec + nt * 8;
            if (p.nsplit > 1) {
                atomicAdd(cp + 0, v0);
                atomicAdd(cp + 1, v1);
                atomicAdd(cp + 8 * (long long)ldc + 0, v2);
                atomicAdd(cp + 8 * (long long)ldc + 1, v3);
            } else {
                *reinterpret_cast<float2*>(cp) = make_float2(v0, v1);
                *reinterpret_cast<float2*>(cp + 8 * (long long)ldc) =
                    make_float2(v2, v3);
            }
        }
    }
}

// ---------------- inv-rms per row ------------------------------------------
__global__ __launch_bounds__(256)
void invnorm_k(const float* __restrict__ h, float* __restrict__ inv)
{
    const int row = blockIdx.x * 8 + (threadIdx.x >> 5);
    const int lane = threadIdx.x & 31;
    const float4* hr = reinterpret_cast<const float4*>(h + (size_t)row * H_);
    float ss = 0.f;
#pragma unroll
    for (int i = 0; i < 32; i++) {
        float4 v = hr[lane + i * 32];
        ss += v.x * v.x + v.y * v.y + v.z * v.z + v.w * v.w;
    }
#pragma unroll
    for (int o = 16; o > 0; o >>= 1) ss += __shfl_xor_sync(0xffffffffu, ss, o);
    if (lane == 0) inv[row] = rsqrtf(ss / (float)H_ + EPS_);
}

// ---------------- RoPE ------------------------------------------------------
__global__ __launch_bounds__(256)
void rope_k(float* __restrict__ q,
            const float* __restrict__ kin, const float* __restrict__ vin,
            const int* __restrict__ pos,
            const float* __restrict__ cosT, const float* __restrict__ sinT,
            float* __restrict__ keys_l, float* __restrict__ vals_l,
            float* __restrict__ vt, float scale)
{
    const int s = blockIdx.x;
    const int p = pos[s];
    const float* cb = cosT + (size_t)p * HD_;
    const float* sb = sinT + (size_t)p * HD_;

#pragma unroll
    for (int i = 0; i < 8; i++) {
        int pi = threadIdx.x + i * 256;
        int hh = pi >> 6, d = pi & 63;
        float c0 = cb[d], c1 = cb[d + 64], s0 = sb[d], s1 = sb[d + 64];
        float* qp = q + (size_t)s * H_ + hh * HD_;
        float a = qp[d], b = qp[d + 64];
        qp[d]      = (a * c0 - b * s0) * scale;
        qp[d + 64] = (b * c1 + a * s1) * scale;
    }
#pragma unroll
    for (int i = 0; i < 2; i++) {
        int pi = threadIdx.x + i * 256;
        int kv = pi >> 6, d = pi & 63;
        float c0 = cb[d], c1 = cb[d + 64], s0 = sb[d], s1 = sb[d + 64];
        const float* kp = kin + (size_t)s * (NKV_ * HD_) + kv * HD_;
        const float* vp = vin + (size_t)s * (NKV_ * HD_) + kv * HD_;
        float a = kp[d], b = kp[d + 64];
        size_t ob = (size_t)kv * S_ * HD_ + (size_t)s * HD_;
        keys_l[ob + d]      = a * c0 - b * s0;
        keys_l[ob + d + 64] = b * c1 + a * s1;
        float v0 = vp[d], v1 = vp[d + 64];
        vals_l[ob + d] = v0;
        vals_l[ob + d + 64] = v1;
        vt[((size_t)kv * HD_ + d) * S_ + s] = v0;
        vt[((size_t)kv * HD_ + d + 64) * S_ + s] = v1;
    }
}

// ------- softmax (mask + softmax; scale pre-folded into Q), causal prefix --
__global__ __launch_bounds__(256)
void softmax_k(float* __restrict__ scores, const float* __restrict__ mask)
{
    const int q = blockIdx.x;
    const int h = blockIdx.y;
    float* row = scores + ((size_t)h * S_ + q) * (size_t)S_;
    const float* m = mask + (size_t)q * S_;
    const int Lq = ((q >> 7) + 1) << 7;
    const int nt = (Lq + 255) >> 8;

    float v[4];
    float mx = -1e30f;
#pragma unroll
    for (int t = 0; t < 4; t++) {
        v[t] = -1e30f;
        if (t < nt) {
            int j = threadIdx.x + t * 256;
            if (j < Lq) {
                v[t] = row[j] + m[j];
                mx = fmaxf(mx, v[t]);
            }
        }
    }
#pragma unroll
    for (int o = 16; o > 0; o >>= 1) mx = fmaxf(mx, __shfl_xor_sync(0xffffffffu, mx, o));
    __shared__ float smx[8];
    __shared__ float ssum[8];
    if ((threadIdx.x & 31) == 0) smx[threadIdx.x >> 5] = mx;
    __syncthreads();
    float rmx = smx[0];
#pragma unroll
    for (int i = 1; i < 8; i++) rmx = fmaxf(rmx, smx[i]);

    float sum = 0.f;
#pragma unroll
    for (int t = 0; t < 4; t++) {
        if (t < nt) {
            int j = threadIdx.x + t * 256;
            if (j < Lq) {
                v[t] = expf(v[t] - rmx);
                sum += v[t];
            }
        }
    }
#pragma unroll
    for (int o = 16; o > 0; o >>= 1) sum += __shfl_xor_sync(0xffffffffu, sum, o);
    if ((threadIdx.x & 31) == 0) ssum[threadIdx.x >> 5] = sum;
    __syncthreads();
    float rsum = ssum[0];
#pragma unroll
    for (int i = 1; i < 8; i++) rsum += ssum[i];
    float inv = 1.f / rsum;
#pragma unroll
    for (int t = 0; t < 4; t++) {
        if (t < nt) {
            int j = threadIdx.x + t * 256;
            if (j < Lq) row[j] = v[t] * inv;
        }
    }
}

// ---------------- silu(gate) * up ------------------------------------------
__global__ __launch_bounds__(256)
void silu_mul_k(float* __restrict__ g, const float* __restrict__ u, long long n)
{
    long long i = (long long)blockIdx.x * 256 + threadIdx.x;
    if (i < n) {
        float x = g[i];
        g[i] = (x / (1.f + expf(-x))) * u[i];
    }
}

// ---------------- launch ----------------------------------------------------
extern "C" void kernel_launch(void* const* d_in, const int* in_sizes, int n_in,
                              void* d_out, int out_size)
{
    const float* x     = (const float*)d_in[0];
    const float* mask  = (const float*)d_in[1];
    const int*   pos   = (const int*)  d_in[2];
    const float* cos_t = (const float*)d_in[3];
    const float* sin_t = (const float*)d_in[4];
    const float* ln1   = (const float*)d_in[5];
    const float* ln2   = (const float*)d_in[6];
    const float* qw    = (const float*)d_in[7];
    const float* kw    = (const float*)d_in[8];
    const float* vw    = (const float*)d_in[9];
    const float* ow    = (const float*)d_in[10];
    const float* gw    = (const float*)d_in[11];
    const float* uw    = (const float*)d_in[12];
    const float* dw    = (const float*)d_in[13];

    float* out  = (float*)d_out;
    float* h    = out;
    float* keys = out + (size_t)S_ * H_;
    float* vals = keys + (size_t)L_ * NKV_ * S_ * HD_;

    float *inv_, *q_, *kv_, *vt_, *sc_, *at_, *ga_, *up_;
    cudaGetSymbolAddress((void**)&inv_, g_inv);
    cudaGetSymbolAddress((void**)&q_,  g_q);
    cudaGetSymbolAddress((void**)&kv_, g_kv);
    cudaGetSymbolAddress((void**)&vt_, g_vt);
    cudaGetSymbolAddress((void**)&sc_, g_sc);
    cudaGetSymbolAddress((void**)&at_, g_at);
    cudaGetSymbolAddress((void**)&ga_, g_ga);
    cudaGetSymbolAddress((void**)&up_, g_up);

    cudaFuncSetAttribute(gemm_ws<3>,
                         cudaFuncAttributeMaxDynamicSharedMemorySize, SMEM_DYN);
    cudaFuncSetAttribute(gemm_ws<2>,
                         cudaFuncAttributeMaxDynamicSharedMemorySize, SMEM_DYN);

    const float scale = 1.f / sqrtf((float)HD_);
    const int BIG = 1 << 30;

    cudaMemcpyAsync(h, x, (size_t)S_ * H_ * sizeof(float),
                    cudaMemcpyDeviceToDevice, 0);

    for (int l = 0; l < L_; l++) {
        const float* qwl = qw + (size_t)l * (NH_ * HD_) * H_;
        const float* kwl = kw + (size_t)l * (NKV_ * HD_) * H_;
        const float* vwl = vw + (size_t)l * (NKV_ * HD_) * H_;
        const float* owl = ow + (size_t)l * H_ * (NH_ * HD_);
        const float* gwl = gw + (size_t)l * IS_ * H_;
        const float* uwl = uw + (size_t)l * IS_ * H_;
        const float* dwl = dw + (size_t)l * H_ * IS_;
        float* keys_l = keys + (size_t)l * NKV_ * S_ * HD_;
        float* vals_l = vals + (size_t)l * NKV_ * S_ * HD_;
        float* kscr = kv_;
        float* vscr = kv_ + (size_t)S_ * NKV_ * HD_;

        // ---- attention block (3-pass: exact-class numerics) ----
        invnorm_k<<<S_ / 8, 256>>>(h, inv_);

        cudaMemsetAsync(q_,  0, (size_t)S_ * H_ * sizeof(float), 0);
        cudaMemsetAsync(kv_, 0, (size_t)2 * S_ * NKV_ * HD_ * sizeof(float), 0);
        {
            GP p = {};
            p.A = h; p.lda = H_; p.sAz = 0;
            p.B0 = qwl; p.C0 = q_;   p.ldb0 = H_; p.ldc0 = H_;
            p.B1 = kwl; p.C1 = kscr; p.ldb1 = H_; p.ldc1 = NKV_ * HD_;
            p.B2 = vwl; p.C2 = vscr; p.ldb2 = H_; p.ldc2 = NKV_ * HD_;
            p.y1 = 32; p.y2 = 40;
            p.sBz = 0; p.sCz = 0; p.zdiv = 1;
            p.K = H_; p.nsplit = 3; p.flags = 0;
            p.w = ln1 + (size_t)l * H_; p.inv = inv_;
            gemm_ws<3><<<dim3(8, 48, 3), 384, SMEM_DYN>>>(p);
        }

        rope_k<<<S_, 256>>>(q_, kscr, vscr, pos, cos_t, sin_t,
                            keys_l, vals_l, vt_, scale);

        {
            GP p = {};
            p.A = q_; p.lda = H_; p.sAz = HD_;
            p.B0 = keys_l; p.C0 = sc_; p.ldb0 = HD_; p.ldc0 = S_;
            p.y1 = BIG; p.y2 = BIG;
            p.sBz = (long long)S_ * HD_; p.sCz = (long long)S_ * S_; p.zdiv = NREP_;
            p.K = HD_; p.nsplit = 1; p.flags = 1;
            gemm_ws<3><<<dim3(8, 8, NH_), 384, SMEM_DYN>>>(p);
        }

        softmax_k<<<dim3(S_, NH_), 256>>>(sc_, mask);

        {
            GP p = {};
            p.A = sc_; p.lda = S_; p.sAz = (long long)S_ * S_;
            p.B0 = vt_; p.C0 = at_; p.ldb0 = S_; p.ldc0 = H_;
            p.y1 = BIG; p.y2 = BIG;
            p.sBz = (long long)HD_ * S_; p.sCz = HD_; p.zdiv = NREP_;
            p.K = S_; p.nsplit = 1; p.flags = 2;
            gemm_ws<3><<<dim3(8, 1, NH_), 384, SMEM_DYN>>>(p);
        }

        {
            GP p = {};
            p.A = at_; p.lda = H_; p.sAz = 0;
            p.B0 = owl; p.C0 = h; p.ldb0 = H_; p.ldc0 = H_;
            p.y1 = BIG; p.y2 = BIG;
            p.sBz = 0; p.sCz = 0; p.zdiv = 1;
            p.K = H_; p.nsplit = 4; p.flags = 0;
            gemm_ws<3><<<dim3(8, 32, 4), 384, SMEM_DYN>>>(p);
        }

        // ---- MLP block (2-pass: B f16-rounded, ~1.4e-4/GEMM) ----
        invnorm_k<<<S_ / 8, 256>>>(h, inv_ + 2048);

        cudaMemsetAsync(ga_, 0, (size_t)S_ * IS_ * sizeof(float), 0);
        cudaMemsetAsync(up_, 0, (size_t)S_ * IS_ * sizeof(float), 0);
        {
            GP p = {};
            p.A = h; p.lda = H_; p.sAz = 0;
            p.B0 = gwl; p.C0 = ga_; p.ldb0 = H_; p.ldc0 = IS_;
            p.B1 = uwl; p.C1 = up_; p.ldb1 = H_; p.ldc1 = IS_;
            p.y1 = 86; p.y2 = BIG;
            p.sBz = 0; p.sCz = 0; p.zdiv = 1;
            p.K = H_; p.nsplit = 2; p.flags = 0;
            p.w = ln2 + (size_t)l * H_; p.inv = inv_ + 2048;
            gemm_ws<2><<<dim3(8, 172, 2), 384, SMEM_DYN>>>(p);
        }

        long long nel = (long long)S_ * IS_;
        silu_mul_k<<<(unsigned)((nel + 255) / 256), 256>>>(ga_, up_, nel);

        {
            GP p = {};
            p.A = ga_; p.lda = IS_; p.sAz = 0;
            p.B0 = dwl; p.C0 = h; p.ldb0 = IS_; p.ldc0 = H_;
            p.y1 = BIG; p.y2 = BIG;
            p.sBz = 0; p.sCz = 0; p.zdiv = 1;
            p.K = IS_; p.nsplit = 4; p.flags = 0;
            gemm_ws<2><<<dim3(8, 32, 4), 384, SMEM_DYN>>>(p);
        }
    }
}